// round 12
// baseline (speedup 1.0000x reference)
#include <cuda_runtime.h>
#include <cuda_bf16.h>
#include <cstdint>
#include <math.h>

#define BB 48
#define SS 128
#define WW 4
#define KK 256
#define KH 128
#define NT 512
#define ROWB 520           // vsm row stride (bytes)
#define ARB  528           // sA row stride (bytes): 512 + 16 pad -> conflict-free LDSM
#define TXB 544u           // 128 alphas + 8 warp maxes

// ---- dynamic smem layout (bytes) ----
#define OFF_SA   0
#define OFF_RING 67584             // 8*256*4
#define OFF_SE   75776             // 2*128*4*4
#define OFF_PAIR 79872             // 2*8*32*16
#define OFF_PMAX 88064             // 8*8*4
#define OFF_REDL 88320             // 4*8*4
#define OFF_TM   88448             // 128*4
#define OFF_RED  88960             // 32*4
#define OFF_MBAR 89088             // 8*8
#define OFF_VSM  89152             // 4*ROWB
#define SMEM_SZ  (OFF_VSM + 4 * ROWB)

typedef unsigned long long ull;

#define MMA_BF16(d0, d1, d2, d3, a0, a1, a2, a3, b0, b1)                      \
    asm volatile(                                                             \
        "mma.sync.aligned.m16n8k16.row.col.f32.bf16.bf16.f32 "                \
        "{%0,%1,%2,%3}, {%4,%5,%6,%7}, {%8,%9}, {%0,%1,%2,%3};"               \
        : "+f"(d0), "+f"(d1), "+f"(d2), "+f"(d3)                              \
        : "r"(a0), "r"(a1), "r"(a2), "r"(a3), "r"(b0), "r"(b1))

#define LDSM_X4(r0, r1, r2, r3, addr)                                         \
    asm volatile("ldmatrix.sync.aligned.m8n8.x4.shared.b16 {%0,%1,%2,%3}, [%4];" \
        : "=r"(r0), "=r"(r1), "=r"(r2), "=r"(r3) : "r"(addr))

static __device__ __forceinline__ uint32_t s2u(const void* p) {
    uint32_t a;
    asm("{ .reg .u64 t; cvta.to.shared.u64 t, %1; cvt.u32.u64 %0, t; }"
        : "=r"(a) : "l"(p));
    return a;
}
static __device__ __forceinline__ uint32_t mapa_u(uint32_t a, int rk) {
    uint32_t r;
    asm("mapa.shared::cluster.u32 %0, %1, %2;" : "=r"(r) : "r"(a), "r"(rk));
    return r;
}
static __device__ __forceinline__ void mbar_init(uint32_t mb, uint32_t cnt) {
    asm volatile("mbarrier.init.shared.b64 [%0], %1;" :: "r"(mb), "r"(cnt) : "memory");
}
static __device__ __forceinline__ void mbar_arm(uint32_t mb, uint32_t tx) {
    asm volatile("mbarrier.arrive.expect_tx.shared.b64 _, [%0], %1;"
                 :: "r"(mb), "r"(tx) : "memory");
}
static __device__ __forceinline__ void st_async_f32(uint32_t dst, float v, uint32_t mb) {
    asm volatile(
        "st.async.weak.shared::cluster.mbarrier::complete_tx::bytes.f32 [%0], %1, [%2];"
        :: "r"(dst), "f"(v), "r"(mb) : "memory");
}
static __device__ __forceinline__ void wait_parity(uint32_t mb, uint32_t par) {
    asm volatile(
        "{\n\t.reg .pred P;\n\t"
        "W_%=:\n\t"
        "mbarrier.try_wait.parity.acquire.cluster.shared::cta.b64 P, [%0], %1, 0x989680;\n\t"
        "@!P bra W_%=;\n\t}"
        :: "r"(mb), "r"(par) : "memory");
}
static __device__ __forceinline__ uint32_t redux_max_u32(uint32_t v) {
    uint32_t r;
    asm("redux.sync.max.u32 %0, %1, 0xffffffff;" : "=r"(r) : "r"(v));
    return r;
}
static __device__ __forceinline__ uint32_t fkey(float f) {
    uint32_t u = __float_as_uint(f);
    return (u & 0x80000000u) ? ~u : (u | 0x80000000u);
}
static __device__ __forceinline__ float funkey(uint32_t k) {
    return __uint_as_float((k & 0x80000000u) ? (k & 0x7fffffffu) : ~k);
}

extern "C" __global__ void __launch_bounds__(NT, 1) __cluster_dims__(2, 1, 1)
crf_hmma5_kernel(const float* __restrict__ logits,
                 const float* __restrict__ T,
                 const float* __restrict__ hc,
                 const float* __restrict__ tagm,
                 const int*   __restrict__ textmask,
                 float* __restrict__ out)
{
    extern __shared__ __align__(16) char smem[];
    float (*sRing)[KK]      = (float(*)[KK])      (smem + OFF_RING);
    float (*sE)[KH][4]      = (float(*)[KH][4])   (smem + OFF_SE);
    float4 (*sPair)[8][32]  = (float4(*)[8][32])  (smem + OFF_PAIR);
    float (*sPmax)[8]       = (float(*)[8])       (smem + OFF_PMAX);
    float (*sRedL)[8]       = (float(*)[8])       (smem + OFF_REDL);
    float* sTm              = (float*)            (smem + OFF_TM);
    float* sRed             = (float*)            (smem + OFF_RED);
    unsigned char* vsm      = (unsigned char*)    (smem + OFF_VSM);

    const int tid  = threadIdx.x;
    const int lane = tid & 31;
    const int wid  = tid >> 5;
    const int b    = blockIdx.x >> 1;
    const int r    = blockIdx.x & 1;
    const int t    = wid & 7;                         // M-tile
    const int khalf = (wid < 8) ? r : (1 - r);        // my kp half

    // ---- length[b] ----
    {
        int tt = (tid < SS) ? textmask[b * SS + tid] : 0;
        #pragma unroll
        for (int o = 16; o; o >>= 1) tt += __shfl_xor_sync(0xffffffffu, tt, o);
        if (lane == 0) sRed[wid] = (float)tt;
    }
    __syncthreads();
    int L = 0;
    #pragma unroll
    for (int i = 0; i < 16; i++) L += (int)sRed[i];
    __syncthreads();
    if (L == 0) { if (r == 0 && tid == 0) out[b] = logf(256.0f); return; }
    const int JMAX = (L < SS) ? L : SS;

    // ---- init barriers ----
    if (tid < 8) {
        mbar_init(s2u(smem + OFF_MBAR) + tid * 8u, 1);
        mbar_arm(s2u(smem + OFF_MBAR) + tid * 8u, TXB);
    }

    // ---- prologue: sA[row][col] = bf16(exp(T*mask)), my M-half x full K ----
    const size_t tb = (size_t)b * KK * KK;
    {
        #pragma unroll 4
        for (int idx = tid; idx < KH * (KK / 2); idx += NT) {
            const int row = idx >> 7;            // local M row 0..127
            const int cp  = (idx & 127) * 2;     // col pair
            const size_t gi = tb + (size_t)(r * KH + row) * KK + cp;
            float2 tv = *(const float2*)(T + gi);
            float2 mv = *(const float2*)(tagm + gi);
            __nv_bfloat162 p =
                __floats2bfloat162_rn(__expf(tv.x * mv.x), __expf(tv.y * mv.y));
            *(uint32_t*)(smem + OFF_SA + row * ARB + cp * 2) = *(uint32_t*)&p;
        }
    }

    // ---- sTm + sE[0] ----
    if (tid < KH) sTm[tid] = tagm[tb + r * KH + tid];
    __syncthreads();
    if (tid < 256) {
        const int k_l = tid >> 1, wp = (tid & 1) * 2;
        const size_t ei = (((size_t)b * SS + 0) * WW + wp) * KK + (r * KH + k_l);
        const float tm = sTm[k_l];
        sE[0][k_l][wp]     = (__ldg(logits + ei     ) + __ldg(hc + ei     )) * tm;
        sE[0][k_l][wp + 1] = (__ldg(logits + ei + KK) + __ldg(hc + ei + KK)) * tm;
    }
    __syncthreads();
    asm volatile("barrier.cluster.arrive.aligned;" ::: "memory");
    asm volatile("barrier.cluster.wait.aligned;"   ::: "memory");

    const int      peer     = 1 - r;
    const uint32_t myMbar   = s2u(smem + OFF_MBAR);
    const uint32_t peerRing = mapa_u(s2u(smem + OFF_RING), peer);
    const uint32_t peerPmax = mapa_u(s2u(smem + OFF_PMAX), peer);
    const uint32_t peerMbar = mapa_u(myMbar, peer);

    // per-warp constant LDSM base: canonical 16x16 A-tile addressing
    const int lr0 = (t << 4) + (lane >> 2);
    const int rg0 = r * KH + lr0;
    const uint32_t aBase = s2u(smem + OFF_SA)
                         + (uint32_t)((t << 4) + (lane & 15)) * ARB
                         + (uint32_t)(lane >> 4) * 16u
                         + (uint32_t)(khalf * 8) * 32u;

    // v-writer mapping
    const int vw   = wid & 7;
    const int vn   = vw & 3;
    const int vkpg = khalf * KH + (vw >> 2) * 64 + lane * 2;
    const uint32_t vdst = (uint32_t)(vn * ROWB + (vkpg << 1));

    float s0 = 0.f, s1 = 0.f, s2 = 0.f, s3 = 0.f;   // stale scales

    for (int j = 0; j < JMAX; j++) {
        const int nT   = (j < WW) ? j : WW;
        const int slot = j & 7;

        if (wid < 8) asm volatile("bar.sync 1, 256;" ::: "memory");

        // ---- stale scale: rowmax_{j-2} ----
        float ns = 0.f;
        if (j >= 2) {
            float x = -1e30f;
            if (lane < 8)       x = sRedL[(j - 2) & 3][lane];
            else if (lane < 16) x = sPmax[(j - 2) & 7][lane - 8];
            ns = funkey(redux_max_u32(fkey(x)));
        }
        s3 = s2; s2 = s1; s1 = s0; s0 = ns;
        float M = (j < WW) ? 0.0f : -1e30f;
        if (nT > 0) M = fmaxf(M, s0);
        if (nT > 1) M = fmaxf(M, s1);
        if (nT > 2) M = fmaxf(M, s2);
        if (nT > 3) M = fmaxf(M, s3);

        float d0 = 0.f, d1 = 0.f, d2 = 0.f, d3 = 0.f;

        if (wid < 8) {
            // ===== group A: v-local -> bar1 =====
            float v0 = 0.f, v1 = 0.f;
            if (vn < j) {
                const float sn = (vn == 0) ? s0 : (vn == 1) ? s1 : (vn == 2) ? s2 : s3;
                float2 rd = *(const float2*)&sRing[(j - 1 - vn) & 7][vkpg];
                v0 = __expf(rd.x - sn);
                v1 = __expf(rd.y - sn);
            }
            __nv_bfloat162 vp = __floats2bfloat162_rn(v0, v1);
            *(uint32_t*)(vsm + vdst) = *(uint32_t*)&vp;
            asm volatile("bar.sync 1, 256;" ::: "memory");
        } else {
            // ===== group B: wait peer alpha -> v-peer -> bar2 =====
            if (j > 0) {
                wait_parity(myMbar + (uint32_t)((j - 1) & 7) * 8u,
                            (uint32_t)(((j - 1) >> 3) & 1));
                if (tid == 288)
                    mbar_arm(myMbar + (uint32_t)((j - 1) & 7) * 8u, TXB);
            }
            float v0 = 0.f, v1 = 0.f;
            if (vn < j) {
                const float sn = (vn == 0) ? s0 : (vn == 1) ? s1 : (vn == 2) ? s2 : s3;
                float2 rd = *(const float2*)&sRing[(j - 1 - vn) & 7][vkpg];
                v0 = __expf(rd.x - sn);
                v1 = __expf(rd.y - sn);
            }
            __nv_bfloat162 vp = __floats2bfloat162_rn(v0, v1);
            *(uint32_t*)(vsm + vdst) = *(uint32_t*)&vp;
            asm volatile("bar.sync 2, 256;" ::: "memory");
        }

        // ---- emission LDGs for j+1 (group B) ----
        float l0 = 0.f, l1 = 0.f, q0 = 0.f, q1 = 0.f;
        int k_l = 0, wp = 0;
        if (wid >= 8 && (j + 1) < JMAX) {
            const int idx = tid & 255;
            k_l = idx >> 1; wp = (idx & 1) * 2;
            const size_t ei = (((size_t)b * SS + (j + 1)) * WW + wp) * KK + (r * KH + k_l);
            l0 = __ldg(logits + ei);      q0 = __ldg(hc + ei);
            l1 = __ldg(logits + ei + KK); q1 = __ldg(hc + ei + KK);
        }

        // ---- MMA: 8 chunks, A via per-chunk LDSM (2 chains of 4) ----
        {
            float f0 = 0.f, f1 = 0.f, f2 = 0.f, f3 = 0.f;
            const int      n8    = lane >> 2;
            const uint32_t bboff = (uint32_t)(lane & 3) << 2;
            #pragma unroll
            for (int c = 0; c < 8; c += 2) {
                uint32_t a0, a1, a2, a3, e0, e1, e2, e3;
                LDSM_X4(a0, a1, a2, a3, aBase + (uint32_t)c * 32u);
                LDSM_X4(e0, e1, e2, e3, aBase + (uint32_t)(c + 1) * 32u);
                uint32_t b0 = 0, b1 = 0, b2 = 0, b3 = 0;
                if (n8 < 4) {
                    const unsigned char* vp =
                        vsm + n8 * ROWB + ((khalf * 8 + c) << 5) + bboff;
                    b0 = *(const uint32_t*)(vp);
                    b1 = *(const uint32_t*)(vp + 16);
                    b2 = *(const uint32_t*)(vp + 32);
                    b3 = *(const uint32_t*)(vp + 48);
                }
                MMA_BF16(d0, d1, d2, d3, a0, a1, a2, a3, b0, b1);
                MMA_BF16(f0, f1, f2, f3, e0, e1, e2, e3, b2, b3);
            }
            d0 += f0; d1 += f1; d2 += f2; d3 += f3;
        }

        if (wid >= 8) sPair[j & 1][t][lane] = make_float4(d0, d1, d2, d3);
        __syncthreads();   // M1

        if (wid < 8) {
            // ===== merge + split epilogue =====
            float4 pp = sPair[j & 1][t][lane];
            d0 += pp.x; d1 += pp.y; d2 += pp.z; d3 += pp.w;

            const int sub = lane & 3;
            float pA = 0.f, pB = 0.f;
            if (sub < 2) {
                const float4 eA4 = *(const float4*)sE[j & 1][lr0];
                const float4 eB4 = *(const float4*)sE[j & 1][lr0 + 8];
                const float ea0 = sub ? eA4.z : eA4.x;
                const float ea1 = sub ? eA4.w : eA4.y;
                const float eb0 = sub ? eB4.z : eB4.x;
                const float eb1 = sub ? eB4.w : eB4.y;
                const float sc0 = sub ? s2 : s0;
                const float sc1 = sub ? s3 : s1;
                const int   w0i = sub << 1;
                if (nT > w0i) {
                    float xA = __expf(ea0 + sc0 - M), xB = __expf(eb0 + sc0 - M);
                    pA += xA * d0;  pB += xB * d2;
                }
                if (nT > w0i + 1) {
                    float xA = __expf(ea1 + sc1 - M), xB = __expf(eb1 + sc1 - M);
                    pA += xA * d1;  pB += xB * d3;
                }
                if (j < WW && (j >> 1) == sub) {
                    float ia = (j & 1) ? ea1 : ea0;
                    float ib = (j & 1) ? eb1 : eb0;
                    pA += 256.0f * __expf(ia - M);
                    pB += 256.0f * __expf(ib - M);
                }
            }
            pA += __shfl_down_sync(0xffffffffu, pA, 1);
            pB += __shfl_down_sync(0xffffffffu, pB, 1);

            float mv = -1e30f;
            if (sub == 0) {
                const float aA = M + __logf(pA);
                const float aB = M + __logf(pB);
                sRing[slot][rg0]     = aA;
                sRing[slot][rg0 + 8] = aB;
                st_async_f32(peerRing + ((uint32_t)(slot * KK + rg0)) * 4u, aA,
                             peerMbar + (uint32_t)slot * 8u);
                st_async_f32(peerRing + ((uint32_t)(slot * KK + rg0 + 8)) * 4u, aB,
                             peerMbar + (uint32_t)slot * 8u);
                mv = fmaxf(aA, aB);
            }
            uint32_t km = redux_max_u32(fkey(mv));
            if (lane == 0) {
                const float wm = funkey(km);
                sRedL[j & 3][t] = wm;
                st_async_f32(peerPmax + ((uint32_t)(slot * 8 + t)) * 4u, wm,
                             peerMbar + (uint32_t)slot * 8u);
            }
        } else if ((j + 1) < JMAX) {
            const float tm = sTm[k_l];
            sE[(j + 1) & 1][k_l][wp]     = (l0 + q0) * tm;
            sE[(j + 1) & 1][k_l][wp + 1] = (l1 + q1) * tm;
        }
        // no trailing sync
    }

    // ---- final: wait last flight, logsumexp over full row ----
    if (wid >= 8)
        wait_parity(myMbar + (uint32_t)((JMAX - 1) & 7) * 8u,
                    (uint32_t)(((JMAX - 1) >> 3) & 1));
    __syncthreads();
    {
        const int fslot = (JMAX - 1) & 7;
        float x = -1e30f;
        if (lane < 8)       x = sRedL[(JMAX - 1) & 3][lane];
        else if (lane < 16) x = sPmax[fslot][lane - 8];
        const float rowmax = funkey(redux_max_u32(fkey(x)));

        float sv = (tid < KK) ? __expf(sRing[fslot][tid] - rowmax) : 0.f;
        #pragma unroll
        for (int o = 16; o; o >>= 1) sv += __shfl_xor_sync(0xffffffffu, sv, o);
        if (lane == 0 && wid < 8) sRed[8 + wid] = sv;
        __syncthreads();
        if (r == 0 && tid == 0) {
            float ssum = 0.f;
            #pragma unroll
            for (int i = 0; i < 8; i++) ssum += sRed[8 + i];
            out[b] = rowmax + __logf(ssum);
        }
    }

    asm volatile("barrier.cluster.arrive.aligned;" ::: "memory");
    asm volatile("barrier.cluster.wait.aligned;"   ::: "memory");
}

// ---------------------------------------------------------------------------
extern "C" void kernel_launch(void* const* d_in, const int* in_sizes, int n_in,
                              void* d_out, int out_size) {
    const float* logits = (const float*)d_in[0];   // (B,S,W,K) f32
    const float* T      = (const float*)d_in[1];   // (B,K,K)   f32
    const float* hc     = (const float*)d_in[2];   // (B,S,W,K) f32
    const float* tagm   = (const float*)d_in[3];   // (B,K,K)   f32
    const int*   tmask  = (const int*)  d_in[4];   // (B,S)     i32
    float* out = (float*)d_out;                    // (1,B)     f32

    cudaFuncSetAttribute(crf_hmma5_kernel,
                         cudaFuncAttributeMaxDynamicSharedMemorySize, SMEM_SZ);
    crf_hmma5_kernel<<<BB * 2, NT, SMEM_SZ>>>(logits, T, hc, tagm, tmask, out);
}

// round 13
// speedup vs baseline: 1.0780x; 1.0780x over previous
#include <cuda_runtime.h>
#include <cuda_bf16.h>
#include <cstdint>
#include <math.h>

#define BB 48
#define SS 128
#define WW 4
#define KK 256
#define KH 128
#define NT 512
#define ROWB 528           // vsm row stride (bytes): 132 words ≡ 4 banks -> conflict-free
#define TXB 544u           // 128 alphas + 8 warp maxes

typedef unsigned long long ull;

#define MMA_BF16(d0, d1, d2, d3, a, b0, b1)                                   \
    asm volatile(                                                             \
        "mma.sync.aligned.m16n8k16.row.col.f32.bf16.bf16.f32 "                \
        "{%0,%1,%2,%3}, {%4,%5,%6,%7}, {%8,%9}, {%0,%1,%2,%3};"               \
        : "+f"(d0), "+f"(d1), "+f"(d2), "+f"(d3)                              \
        : "r"((a)[0]), "r"((a)[1]), "r"((a)[2]), "r"((a)[3]),                 \
          "r"(b0), "r"(b1))

static __device__ __forceinline__ uint32_t s2u(const void* p) {
    uint32_t a;
    asm("{ .reg .u64 t; cvta.to.shared.u64 t, %1; cvt.u32.u64 %0, t; }"
        : "=r"(a) : "l"(p));
    return a;
}
static __device__ __forceinline__ uint32_t mapa_u(uint32_t a, int rk) {
    uint32_t r;
    asm("mapa.shared::cluster.u32 %0, %1, %2;" : "=r"(r) : "r"(a), "r"(rk));
    return r;
}
static __device__ __forceinline__ void mbar_init(uint32_t mb, uint32_t cnt) {
    asm volatile("mbarrier.init.shared.b64 [%0], %1;" :: "r"(mb), "r"(cnt) : "memory");
}
static __device__ __forceinline__ void mbar_arm(uint32_t mb, uint32_t tx) {
    asm volatile("mbarrier.arrive.expect_tx.shared.b64 _, [%0], %1;"
                 :: "r"(mb), "r"(tx) : "memory");
}
static __device__ __forceinline__ void st_async_f32(uint32_t dst, float v, uint32_t mb) {
    asm volatile(
        "st.async.weak.shared::cluster.mbarrier::complete_tx::bytes.f32 [%0], %1, [%2];"
        :: "r"(dst), "f"(v), "r"(mb) : "memory");
}
static __device__ __forceinline__ void wait_parity(uint32_t mb, uint32_t par) {
    asm volatile(
        "{\n\t.reg .pred P;\n\t"
        "W_%=:\n\t"
        "mbarrier.try_wait.parity.acquire.cluster.shared::cta.b64 P, [%0], %1, 0x989680;\n\t"
        "@!P bra W_%=;\n\t}"
        :: "r"(mb), "r"(par) : "memory");
}
static __device__ __forceinline__ uint32_t redux_max_u32(uint32_t v) {
    uint32_t r;
    asm("redux.sync.max.u32 %0, %1, 0xffffffff;" : "=r"(r) : "r"(v));
    return r;
}
static __device__ __forceinline__ uint32_t fkey(float f) {
    uint32_t u = __float_as_uint(f);
    return (u & 0x80000000u) ? ~u : (u | 0x80000000u);
}
static __device__ __forceinline__ float funkey(uint32_t k) {
    return __uint_as_float((k & 0x80000000u) ? (k & 0x7fffffffu) : ~k);
}

extern "C" __global__ void __launch_bounds__(NT, 1) __cluster_dims__(2, 1, 1)
crf_hmma6_kernel(const float* __restrict__ logits,
                 const float* __restrict__ T,
                 const float* __restrict__ hc,
                 const float* __restrict__ tagm,
                 const int*   __restrict__ textmask,
                 float* __restrict__ out)
{
    __shared__ float  sRing[8][KK];       // alpha ring, full rows
    __shared__ float  sE[2][KH][4];       // emissions, double-buffered
    __shared__ float4 sPair[2][8][32];    // chunkset-1 partials
    __shared__ float  sPmax[8][8];        // peer warp maxes per slot
    __shared__ float  sRedL[4][8];        // local warp maxes (4-slot ring)
    __shared__ float  sTm[KH];
    __shared__ float  sRed[32];
    __shared__ ull    sMbar[8];
    __shared__ __align__(4) unsigned char vsm[4 * ROWB];

    const int tid  = threadIdx.x;
    const int lane = tid & 31;
    const int wid  = tid >> 5;
    const int b    = blockIdx.x >> 1;
    const int r    = blockIdx.x & 1;
    const int t    = wid & 7;                    // M-tile
    const int h    = wid >> 3;                   // chunk quartet 0/1
    const int cL   = r * 8 + h * 4;              // local chunk base (global)
    const int cP   = (1 - r) * 8 + h * 4;        // peer chunk base

    // ---- length[b] ----
    {
        int tt = (tid < SS) ? textmask[b * SS + tid] : 0;
        #pragma unroll
        for (int o = 16; o; o >>= 1) tt += __shfl_xor_sync(0xffffffffu, tt, o);
        if (lane == 0) sRed[wid] = (float)tt;
    }
    __syncthreads();
    int L = 0;
    #pragma unroll
    for (int i = 0; i < 16; i++) L += (int)sRed[i];
    __syncthreads();
    if (L == 0) { if (r == 0 && tid == 0) out[b] = logf(256.0f); return; }
    const int JMAX = (L < SS) ? L : SS;

    // ---- init barriers ----
    if (tid < 8) {
        mbar_init(s2u(&sMbar[tid]), 1);
        mbar_arm(s2u(&sMbar[tid]), TXB);
    }

    // ---- prologue: A frags in regs (4 local + 4 peer chunks), rows rg0/rg0+8 ----
    const size_t tb  = (size_t)b * KK * KK;
    const int    lr0 = (t << 4) + (lane >> 2);
    const int    rg0 = r * KH + lr0;
    const int    kq  = (lane & 3) << 1;
    uint32_t A[8][4];
    {
        const float* Tr0 = T    + tb + (size_t)rg0 * KK;
        const float* Mr0 = tagm + tb + (size_t)rg0 * KK;
        const float* Tr1 = Tr0 + 8 * KK;
        const float* Mr1 = Mr0 + 8 * KK;
        #pragma unroll
        for (int i = 0; i < 8; i++) {
            const int cg = (i < 4) ? (cL + i) : (cP + (i - 4));
            #pragma unroll
            for (int h2 = 0; h2 < 2; h2++) {
                const int kk2 = cg * 16 + kq + h2 * 8;
                float2 t0 = *(const float2*)(Tr0 + kk2);
                float2 m0 = *(const float2*)(Mr0 + kk2);
                float2 t1 = *(const float2*)(Tr1 + kk2);
                float2 m1 = *(const float2*)(Mr1 + kk2);
                __nv_bfloat162 p0 =
                    __floats2bfloat162_rn(__expf(t0.x * m0.x), __expf(t0.y * m0.y));
                __nv_bfloat162 p1 =
                    __floats2bfloat162_rn(__expf(t1.x * m1.x), __expf(t1.y * m1.y));
                A[i][h2 * 2 + 0] = *(uint32_t*)&p0;
                A[i][h2 * 2 + 1] = *(uint32_t*)&p1;
            }
        }
    }

    // ---- sTm + sE[0] ----
    if (tid < KH) sTm[tid] = tagm[tb + r * KH + tid];
    __syncthreads();
    if (tid < 256) {
        const int k_l = tid >> 1, wp = (tid & 1) * 2;
        const size_t ei = (((size_t)b * SS + 0) * WW + wp) * KK + (r * KH + k_l);
        const float tm = sTm[k_l];
        sE[0][k_l][wp]     = (__ldg(logits + ei     ) + __ldg(hc + ei     )) * tm;
        sE[0][k_l][wp + 1] = (__ldg(logits + ei + KK) + __ldg(hc + ei + KK)) * tm;
    }
    __syncthreads();
    asm volatile("barrier.cluster.arrive.aligned;" ::: "memory");
    asm volatile("barrier.cluster.wait.aligned;"   ::: "memory");

    const int      peer     = 1 - r;
    const uint32_t myMbar   = s2u(sMbar);
    const uint32_t peerRing = mapa_u(s2u(sRing), peer);
    const uint32_t peerPmax = mapa_u(s2u(sPmax), peer);
    const uint32_t peerMbar = mapa_u(myMbar, peer);

    float s0 = 0.f, s1 = 0.f, s2 = 0.f, s3 = 0.f;   // stale scales (newest first)

    for (int j = 0; j < JMAX; j++) {
        const int nT   = (j < WW) ? j : WW;
        const int slot = j & 7;

        // epilogue warps (0-7) must all finish writing sRing before v reads
        if (wid < 8) asm volatile("bar.sync 1, 256;" ::: "memory");

        // ---- stale scale: rowmax_{j-2} via per-warp redux ----
        float ns = 0.f;
        if (j >= 2) {
            float x = -1e30f;
            if (lane < 8)       x = sRedL[(j - 2) & 3][lane];
            else if (lane < 16) x = sPmax[(j - 2) & 7][lane - 8];
            ns = funkey(redux_max_u32(fkey(x)));
        }
        s3 = s2; s2 = s1; s1 = s0; s0 = ns;
        float M = (j < WW) ? 0.0f : -1e30f;
        if (nT > 0) M = fmaxf(M, s0);
        if (nT > 1) M = fmaxf(M, s1);
        if (nT > 2) M = fmaxf(M, s2);
        if (nT > 3) M = fmaxf(M, s3);

        // ---- top v-writes: local rows 0-3 (tid<256), peer rows 1-3 (tid>=256) ----
        {
            int n = -1, kpf = 0;
            if (tid < 256) { n = tid >> 6; kpf = r * KH + (tid & 63) * 2; }
            else if ((tid - 256) < 192) {
                const int idx = tid - 256;
                n = 1 + (idx >> 6); kpf = (1 - r) * KH + (idx & 63) * 2;
            }
            if (n >= 0) {
                float v0 = 0.f, v1 = 0.f;
                if (n < j) {
                    const float sn = (n == 0) ? s0 : (n == 1) ? s1 : (n == 2) ? s2 : s3;
                    float2 rd = *(const float2*)&sRing[(j - 1 - n) & 7][kpf];
                    v0 = __expf(rd.x - sn);
                    v1 = __expf(rd.y - sn);
                }
                __nv_bfloat162 vp = __floats2bfloat162_rn(v0, v1);
                *(uint32_t*)(vsm + n * ROWB + (kpf << 1)) = *(uint32_t*)&vp;
            }
        }
        __syncthreads();   // S_top: v (except peer row0) ready

        // ---- local-phase MMA: 4 chunks (no wait needed) ----
        float d0 = 0.f, d1 = 0.f, d2 = 0.f, d3 = 0.f;
        float f0 = 0.f, f1 = 0.f, f2 = 0.f, f3 = 0.f;
        const int      n8    = lane >> 2;
        const uint32_t bboff = (uint32_t)(lane & 3) << 2;
        #pragma unroll
        for (int i = 0; i < 4; i += 2) {
            uint32_t b0 = 0, b1 = 0, b2 = 0, b3 = 0;
            if (n8 < 4) {
                const unsigned char* vp = vsm + n8 * ROWB + ((cL + i) << 5) + bboff;
                b0 = *(const uint32_t*)(vp);
                b1 = *(const uint32_t*)(vp + 16);
                b2 = *(const uint32_t*)(vp + 32);
                b3 = *(const uint32_t*)(vp + 48);
            }
            MMA_BF16(d0, d1, d2, d3, A[i],     b0, b1);
            MMA_BF16(f0, f1, f2, f3, A[i + 1], b2, b3);
        }

        // ---- emission LDGs for j+1 (warps 8-15, hidden under wait/MMA) ----
        float l0 = 0.f, l1 = 0.f, q0 = 0.f, q1 = 0.f;
        int k_l = 0, wp = 0;
        if (wid >= 8 && (j + 1) < JMAX) {
            const int idx = tid & 255;
            k_l = idx >> 1; wp = (idx & 1) * 2;
            const size_t ei = (((size_t)b * SS + (j + 1)) * WW + wp) * KK + (r * KH + k_l);
            l0 = __ldg(logits + ei);      q0 = __ldg(hc + ei);
            l1 = __ldg(logits + ei + KK); q1 = __ldg(hc + ei + KK);
        }

        // ---- mid: warps 0-1 absorb the flight, write peer row0 ----
        if (wid < 2) {
            if (j > 0) {
                wait_parity(myMbar + (uint32_t)((j - 1) & 7) * 8u,
                            (uint32_t)(((j - 1) >> 3) & 1));
                if (tid == 0)
                    mbar_arm(myMbar + (uint32_t)((j - 1) & 7) * 8u, TXB);
            }
            const int kpf = (1 - r) * KH + (wid * 32 + lane) * 2;
            float v0 = 0.f, v1 = 0.f;
            if (j > 0) {
                float2 rd = *(const float2*)&sRing[(j - 1) & 7][kpf];
                v0 = __expf(rd.x - s0);
                v1 = __expf(rd.y - s0);
            }
            __nv_bfloat162 vp = __floats2bfloat162_rn(v0, v1);
            *(uint32_t*)(vsm + (kpf << 1)) = *(uint32_t*)&vp;
        }
        __syncthreads();   // S_mid: peer row0 ready

        // ---- peer-phase MMA: 4 chunks ----
        #pragma unroll
        for (int i = 0; i < 4; i += 2) {
            uint32_t b0 = 0, b1 = 0, b2 = 0, b3 = 0;
            if (n8 < 4) {
                const unsigned char* vp = vsm + n8 * ROWB + ((cP + i) << 5) + bboff;
                b0 = *(const uint32_t*)(vp);
                b1 = *(const uint32_t*)(vp + 16);
                b2 = *(const uint32_t*)(vp + 32);
                b3 = *(const uint32_t*)(vp + 48);
            }
            MMA_BF16(d0, d1, d2, d3, A[4 + i],     b0, b1);
            MMA_BF16(f0, f1, f2, f3, A[4 + i + 1], b2, b3);
        }
        d0 += f0; d1 += f1; d2 += f2; d3 += f3;

        if (wid >= 8) sPair[j & 1][t][lane] = make_float4(d0, d1, d2, d3);
        __syncthreads();   // M1

        if (wid < 8) {
            // ===== merge + split epilogue =====
            float4 pp = sPair[j & 1][t][lane];
            d0 += pp.x; d1 += pp.y; d2 += pp.z; d3 += pp.w;

            const int sub = lane & 3;
            float pA = 0.f, pB = 0.f;
            if (sub < 2) {
                const float4 eA4 = *(const float4*)sE[j & 1][lr0];
                const float4 eB4 = *(const float4*)sE[j & 1][lr0 + 8];
                const float ea0 = sub ? eA4.z : eA4.x;
                const float ea1 = sub ? eA4.w : eA4.y;
                const float eb0 = sub ? eB4.z : eB4.x;
                const float eb1 = sub ? eB4.w : eB4.y;
                const float sc0 = sub ? s2 : s0;
                const float sc1 = sub ? s3 : s1;
                const int   w0i = sub << 1;
                if (nT > w0i) {
                    float xA = __expf(ea0 + sc0 - M), xB = __expf(eb0 + sc0 - M);
                    pA += xA * d0;  pB += xB * d2;
                }
                if (nT > w0i + 1) {
                    float xA = __expf(ea1 + sc1 - M), xB = __expf(eb1 + sc1 - M);
                    pA += xA * d1;  pB += xB * d3;
                }
                if (j < WW && (j >> 1) == sub) {   // initial-state (zeros) row
                    float ia = (j & 1) ? ea1 : ea0;
                    float ib = (j & 1) ? eb1 : eb0;
                    pA += 256.0f * __expf(ia - M);
                    pB += 256.0f * __expf(ib - M);
                }
            }
            pA += __shfl_down_sync(0xffffffffu, pA, 1);
            pB += __shfl_down_sync(0xffffffffu, pB, 1);

            float mv = -1e30f;
            if (sub == 0) {
                const float aA = M + __logf(pA);
                const float aB = M + __logf(pB);
                sRing[slot][rg0]     = aA;
                sRing[slot][rg0 + 8] = aB;
                st_async_f32(peerRing + ((uint32_t)(slot * KK + rg0)) * 4u, aA,
                             peerMbar + (uint32_t)slot * 8u);
                st_async_f32(peerRing + ((uint32_t)(slot * KK + rg0 + 8)) * 4u, aB,
                             peerMbar + (uint32_t)slot * 8u);
                mv = fmaxf(aA, aB);
            }
            uint32_t km = redux_max_u32(fkey(mv));
            if (lane == 0) {
                const float wm = funkey(km);
                sRedL[j & 3][t] = wm;
                st_async_f32(peerPmax + ((uint32_t)(slot * 8 + t)) * 4u, wm,
                             peerMbar + (uint32_t)slot * 8u);
            }
        } else if ((j + 1) < JMAX) {
            // ===== warps 8-15: stage next emissions =====
            const float tm = sTm[k_l];
            sE[(j + 1) & 1][k_l][wp]     = (l0 + q0) * tm;
            sE[(j + 1) & 1][k_l][wp + 1] = (l1 + q1) * tm;
        }
        // no trailing sync: S_top / bar1 of next step provide ordering
    }

    // ---- final: wait last flight (warps 0-1), then logsumexp over full row ----
    if (wid < 2)
        wait_parity(myMbar + (uint32_t)((JMAX - 1) & 7) * 8u,
                    (uint32_t)(((JMAX - 1) >> 3) & 1));
    __syncthreads();
    {
        const int fslot = (JMAX - 1) & 7;
        float x = -1e30f;
        if (lane < 8)       x = sRedL[(JMAX - 1) & 3][lane];
        else if (lane < 16) x = sPmax[fslot][lane - 8];
        const float rowmax = funkey(redux_max_u32(fkey(x)));

        float sv = (tid < KK) ? __expf(sRing[fslot][tid] - rowmax) : 0.f;
        #pragma unroll
        for (int o = 16; o; o >>= 1) sv += __shfl_xor_sync(0xffffffffu, sv, o);
        if (lane == 0 && wid < 8) sRed[8 + wid] = sv;
        __syncthreads();
        if (r == 0 && tid == 0) {
            float ssum = 0.f;
            #pragma unroll
            for (int i = 0; i < 8; i++) ssum += sRed[8 + i];
            out[b] = rowmax + __logf(ssum);
        }
    }

    asm volatile("barrier.cluster.arrive.aligned;" ::: "memory");
    asm volatile("barrier.cluster.wait.aligned;"   ::: "memory");
}

// ---------------------------------------------------------------------------
extern "C" void kernel_launch(void* const* d_in, const int* in_sizes, int n_in,
                              void* d_out, int out_size) {
    const float* logits = (const float*)d_in[0];   // (B,S,W,K) f32
    const float* T      = (const float*)d_in[1];   // (B,K,K)   f32
    const float* hc     = (const float*)d_in[2];   // (B,S,W,K) f32
    const float* tagm   = (const float*)d_in[3];   // (B,K,K)   f32
    const int*   tmask  = (const int*)  d_in[4];   // (B,S)     i32
    float* out = (float*)d_out;                    // (1,B)     f32

    crf_hmma6_kernel<<<BB * 2, NT>>>(logits, T, hc, tagm, tmask, out);
}

// round 14
// speedup vs baseline: 1.2909x; 1.1976x over previous
#include <cuda_runtime.h>
#include <cuda_bf16.h>
#include <cstdint>
#include <math.h>

#define BB 48
#define SS 128
#define WW 4
#define KK 256
#define KH 128
#define NT 512
#define ROWB 528           // v-ring slot stride (bytes): 132 words -> conflict-free
#define TXB 544u           // 128 alphas + 8 warp maxes

typedef unsigned long long ull;

#define MMA_BF16(d0, d1, d2, d3, a, b0, b1)                                   \
    asm volatile(                                                             \
        "mma.sync.aligned.m16n8k16.row.col.f32.bf16.bf16.f32 "                \
        "{%0,%1,%2,%3}, {%4,%5,%6,%7}, {%8,%9}, {%0,%1,%2,%3};"               \
        : "+f"(d0), "+f"(d1), "+f"(d2), "+f"(d3)                              \
        : "r"((a)[0]), "r"((a)[1]), "r"((a)[2]), "r"((a)[3]),                 \
          "r"(b0), "r"(b1))

static __device__ __forceinline__ uint32_t s2u(const void* p) {
    uint32_t a;
    asm("{ .reg .u64 t; cvta.to.shared.u64 t, %1; cvt.u32.u64 %0, t; }"
        : "=r"(a) : "l"(p));
    return a;
}
static __device__ __forceinline__ uint32_t mapa_u(uint32_t a, int rk) {
    uint32_t r;
    asm("mapa.shared::cluster.u32 %0, %1, %2;" : "=r"(r) : "r"(a), "r"(rk));
    return r;
}
static __device__ __forceinline__ void mbar_init(uint32_t mb, uint32_t cnt) {
    asm volatile("mbarrier.init.shared.b64 [%0], %1;" :: "r"(mb), "r"(cnt) : "memory");
}
static __device__ __forceinline__ void mbar_arm(uint32_t mb, uint32_t tx) {
    asm volatile("mbarrier.arrive.expect_tx.shared.b64 _, [%0], %1;"
                 :: "r"(mb), "r"(tx) : "memory");
}
static __device__ __forceinline__ void st_async_f32(uint32_t dst, float v, uint32_t mb) {
    asm volatile(
        "st.async.weak.shared::cluster.mbarrier::complete_tx::bytes.f32 [%0], %1, [%2];"
        :: "r"(dst), "f"(v), "r"(mb) : "memory");
}
static __device__ __forceinline__ void wait_parity(uint32_t mb, uint32_t par) {
    asm volatile(
        "{\n\t.reg .pred P;\n\t"
        "W_%=:\n\t"
        "mbarrier.try_wait.parity.acquire.cluster.shared::cta.b64 P, [%0], %1, 0x989680;\n\t"
        "@!P bra W_%=;\n\t}"
        :: "r"(mb), "r"(par) : "memory");
}
static __device__ __forceinline__ uint32_t redux_max_u32(uint32_t v) {
    uint32_t r;
    asm("redux.sync.max.u32 %0, %1, 0xffffffff;" : "=r"(r) : "r"(v));
    return r;
}
static __device__ __forceinline__ uint32_t fkey(float f) {
    uint32_t u = __float_as_uint(f);
    return (u & 0x80000000u) ? ~u : (u | 0x80000000u);
}
static __device__ __forceinline__ float funkey(uint32_t k) {
    return __uint_as_float((k & 0x80000000u) ? (k & 0x7fffffffu) : ~k);
}

extern "C" __global__ void __launch_bounds__(NT, 1) __cluster_dims__(2, 1, 1)
crf_hmma7_kernel(const float* __restrict__ logits,
                 const float* __restrict__ T,
                 const float* __restrict__ hc,
                 const float* __restrict__ tagm,
                 const int*   __restrict__ textmask,
                 float* __restrict__ out)
{
    __shared__ float  sRing[8][KK];       // alpha ring (f32, for exchange + final)
    __shared__ float  sE[2][KH][4];       // emissions, double-buffered
    __shared__ float4 sPair[2][8][32];    // group B partials, double-buffered
    __shared__ float  sPmax[8][8];        // peer warp maxes per slot
    __shared__ float  sRedL[4][8];        // local warp maxes (4-slot ring)
    __shared__ float  sTm[KH];
    __shared__ float  sRed[32];
    __shared__ ull    sMbar[8];
    __shared__ __align__(4) unsigned char vsm[8 * ROWB];   // bf16 v-ring, 8 slots

    const int tid  = threadIdx.x;
    const int lane = tid & 31;
    const int wid  = tid >> 5;
    const int b    = blockIdx.x >> 1;
    const int r    = blockIdx.x & 1;
    const int t    = wid & 7;                         // M-tile
    const int khalf = (wid < 8) ? r : (1 - r);        // my kp half

    // ---- length[b] ----
    {
        int tt = (tid < SS) ? textmask[b * SS + tid] : 0;
        #pragma unroll
        for (int o = 16; o; o >>= 1) tt += __shfl_xor_sync(0xffffffffu, tt, o);
        if (lane == 0) sRed[wid] = (float)tt;
    }
    __syncthreads();
    int L = 0;
    #pragma unroll
    for (int i = 0; i < 16; i++) L += (int)sRed[i];
    __syncthreads();
    if (L == 0) { if (r == 0 && tid == 0) out[b] = logf(256.0f); return; }
    const int JMAX = (L < SS) ? L : SS;

    // ---- init barriers + zero v-ring ----
    if (tid < 8) {
        mbar_init(s2u(&sMbar[tid]), 1);
        mbar_arm(s2u(&sMbar[tid]), TXB);
    }
    {
        uint32_t* vz = (uint32_t*)vsm;
        for (int i = tid; i < (8 * ROWB) / 4; i += NT) vz[i] = 0u;
    }

    // ---- prologue: A frags (my kp half), rows rg0 / rg0+8 ----
    const size_t tb  = (size_t)b * KK * KK;
    const int    lr0 = (t << 4) + (lane >> 2);
    const int    rg0 = r * KH + lr0;
    const int    kq  = (lane & 3) << 1;
    uint32_t A[8][4];
    {
        const float* Tr0 = T    + tb + (size_t)rg0 * KK;
        const float* Mr0 = tagm + tb + (size_t)rg0 * KK;
        const float* Tr1 = Tr0 + 8 * KK;
        const float* Mr1 = Mr0 + 8 * KK;
        #pragma unroll
        for (int c = 0; c < 8; c++) {
            #pragma unroll
            for (int h2 = 0; h2 < 2; h2++) {
                const int kk2 = (khalf * 8 + c) * 16 + kq + h2 * 8;
                float2 t0 = *(const float2*)(Tr0 + kk2);
                float2 m0 = *(const float2*)(Mr0 + kk2);
                float2 t1 = *(const float2*)(Tr1 + kk2);
                float2 m1 = *(const float2*)(Mr1 + kk2);
                __nv_bfloat162 p0 =
                    __floats2bfloat162_rn(__expf(t0.x * m0.x), __expf(t0.y * m0.y));
                __nv_bfloat162 p1 =
                    __floats2bfloat162_rn(__expf(t1.x * m1.x), __expf(t1.y * m1.y));
                A[c][h2 * 2 + 0] = *(uint32_t*)&p0;
                A[c][h2 * 2 + 1] = *(uint32_t*)&p1;
            }
        }
    }

    // ---- sTm + sE[0] ----
    if (tid < KH) sTm[tid] = tagm[tb + r * KH + tid];
    __syncthreads();
    if (tid < 256) {
        const int k_l = tid >> 1, wp = (tid & 1) * 2;
        const size_t ei = (((size_t)b * SS + 0) * WW + wp) * KK + (r * KH + k_l);
        const float tm = sTm[k_l];
        sE[0][k_l][wp]     = (__ldg(logits + ei     ) + __ldg(hc + ei     )) * tm;
        sE[0][k_l][wp + 1] = (__ldg(logits + ei + KK) + __ldg(hc + ei + KK)) * tm;
    }
    __syncthreads();
    asm volatile("barrier.cluster.arrive.aligned;" ::: "memory");
    asm volatile("barrier.cluster.wait.aligned;"   ::: "memory");

    const int      peer     = 1 - r;
    const uint32_t myMbar   = s2u(sMbar);
    const uint32_t peerRing = mapa_u(s2u(sRing), peer);
    const uint32_t peerPmax = mapa_u(s2u(sPmax), peer);
    const uint32_t peerMbar = mapa_u(myMbar, peer);

    // σ history: s0 = σ_j (scale for row written THIS step) = rowmax_{j-2};
    // epilogue w=n uses σ_{j-1-n} = s_{n+1}.
    float s0 = 0.f, s1 = 0.f, s2 = 0.f, s3 = 0.f, s4 = 0.f;

    for (int j = 0; j < JMAX; j++) {
        const int nT   = (j < WW) ? j : WW;
        const int slot = j & 7;

        // ---- σ shift: s0 = rowmax_{j-2} (per-warp redux, off critical data) ----
        float ns = 0.f;
        if (j >= 2) {
            float x = -1e30f;
            if (lane < 8)       x = sRedL[(j - 2) & 3][lane];
            else if (lane < 16) x = sPmax[(j - 2) & 7][lane - 8];
            ns = funkey(redux_max_u32(fkey(x)));
        }
        s4 = s3; s3 = s2; s2 = s1; s1 = s0; s0 = ns;
        float M = (j < WW) ? 0.0f : -1e30f;
        if (nT > 0) M = fmaxf(M, s1);
        if (nT > 1) M = fmaxf(M, s2);
        if (nT > 2) M = fmaxf(M, s3);
        if (nT > 3) M = fmaxf(M, s4);

        // ---- group B: wait peer alphas of row j-1, write peer half of v slot j-1 ----
        if (wid >= 8 && j > 0) {
            wait_parity(myMbar + (uint32_t)((j - 1) & 7) * 8u,
                        (uint32_t)(((j - 1) >> 3) & 1));
            if (tid == 288)
                mbar_arm(myMbar + (uint32_t)((j - 1) & 7) * 8u, TXB);
            const int idx = tid & 255;
            if (idx < 64) {   // 64 lanes x bf16x2 = 128 values (peer half)
                const int kpf = peer * KH + idx * 2;
                float2 rd = *(const float2*)&sRing[(j - 1) & 7][kpf];
                // σ_{j-1} = s1
                __nv_bfloat162 vp =
                    __floats2bfloat162_rn(__expf(rd.x - s1), __expf(rd.y - s1));
                *(uint32_t*)(vsm + ((j - 1) & 7) * ROWB + (kpf << 1)) = *(uint32_t*)&vp;
            }
        }
        __syncthreads();   // bar0: v-ring rows (j-1..j-4) complete for both halves

        // ---- emission LDGs for j+1 (group B) ----
        float l0 = 0.f, l1 = 0.f, q0 = 0.f, q1 = 0.f;
        int k_l = 0, wp = 0;
        if (wid >= 8 && (j + 1) < JMAX) {
            const int idx = tid & 255;
            k_l = idx >> 1; wp = (idx & 1) * 2;
            const size_t ei = (((size_t)b * SS + (j + 1)) * WW + wp) * KK + (r * KH + k_l);
            l0 = __ldg(logits + ei);      q0 = __ldg(hc + ei);
            l1 = __ldg(logits + ei + KK); q1 = __ldg(hc + ei + KK);
        }

        // ---- MMA over my kp half: B rows = ring slots (j-1-n8)&7 ----
        float d0 = 0.f, d1 = 0.f, d2 = 0.f, d3 = 0.f;
        {
            float f0 = 0.f, f1 = 0.f, f2 = 0.f, f3 = 0.f;
            const int      n8    = lane >> 2;
            const uint32_t bboff = (uint32_t)(lane & 3) << 2;
            const uint32_t rowoff =
                (uint32_t)((j - 1 - n8) & 7) * ROWB + (uint32_t)((khalf * 8) << 5) + bboff;
            #pragma unroll
            for (int c = 0; c < 8; c += 2) {
                uint32_t b0 = 0, b1 = 0, b2 = 0, b3 = 0;
                if (n8 < 4) {
                    const unsigned char* vp = vsm + rowoff + (c << 5);
                    b0 = *(const uint32_t*)(vp);
                    b1 = *(const uint32_t*)(vp + 16);
                    b2 = *(const uint32_t*)(vp + 32);
                    b3 = *(const uint32_t*)(vp + 48);
                }
                MMA_BF16(d0, d1, d2, d3, A[c],     b0, b1);
                MMA_BF16(f0, f1, f2, f3, A[c + 1], b2, b3);
            }
            d0 += f0; d1 += f1; d2 += f2; d3 += f3;
        }

        if (wid >= 8) sPair[j & 1][t][lane] = make_float4(d0, d1, d2, d3);
        __syncthreads();   // M1

        if (wid < 8) {
            // ===== merge + split epilogue (w=n uses scale s_{n+1}) =====
            float4 pp = sPair[j & 1][t][lane];
            d0 += pp.x; d1 += pp.y; d2 += pp.z; d3 += pp.w;

            const int sub = lane & 3;
            float pA = 0.f, pB = 0.f;
            if (sub < 2) {
                const float4 eA4 = *(const float4*)sE[j & 1][lr0];
                const float4 eB4 = *(const float4*)sE[j & 1][lr0 + 8];
                const float ea0 = sub ? eA4.z : eA4.x;
                const float ea1 = sub ? eA4.w : eA4.y;
                const float eb0 = sub ? eB4.z : eB4.x;
                const float eb1 = sub ? eB4.w : eB4.y;
                const float sc0 = sub ? s3 : s1;   // w2 : w0
                const float sc1 = sub ? s4 : s2;   // w3 : w1
                const int   w0i = sub << 1;
                if (nT > w0i) {
                    float xA = __expf(ea0 + sc0 - M), xB = __expf(eb0 + sc0 - M);
                    pA += xA * d0;  pB += xB * d2;
                }
                if (nT > w0i + 1) {
                    float xA = __expf(ea1 + sc1 - M), xB = __expf(eb1 + sc1 - M);
                    pA += xA * d1;  pB += xB * d3;
                }
                if (j < WW && (j >> 1) == sub) {   // initial-state (zeros) row
                    float ia = (j & 1) ? ea1 : ea0;
                    float ib = (j & 1) ? eb1 : eb0;
                    pA += 256.0f * __expf(ia - M);
                    pB += 256.0f * __expf(ib - M);
                }
            }
            pA += __shfl_down_sync(0xffffffffu, pA, 1);
            pB += __shfl_down_sync(0xffffffffu, pB, 1);

            float mv = -1e30f;
            if (sub == 0) {
                const float aA = M + __logf(pA);
                const float aB = M + __logf(pB);
                sRing[slot][rg0]     = aA;
                sRing[slot][rg0 + 8] = aB;
                // local half of v-ring row j, scale σ_j = s0 (in-register, once)
                __nv_bfloat16 vA = __float2bfloat16(__expf(aA - s0));
                __nv_bfloat16 vB = __float2bfloat16(__expf(aB - s0));
                *(__nv_bfloat16*)(vsm + slot * ROWB + (rg0 << 1))       = vA;
                *(__nv_bfloat16*)(vsm + slot * ROWB + ((rg0 + 8) << 1)) = vB;
                st_async_f32(peerRing + ((uint32_t)(slot * KK + rg0)) * 4u, aA,
                             peerMbar + (uint32_t)slot * 8u);
                st_async_f32(peerRing + ((uint32_t)(slot * KK + rg0 + 8)) * 4u, aB,
                             peerMbar + (uint32_t)slot * 8u);
                mv = fmaxf(aA, aB);
            }
            uint32_t km = redux_max_u32(fkey(mv));
            if (lane == 0) {
                const float wm = funkey(km);
                sRedL[j & 3][t] = wm;
                st_async_f32(peerPmax + ((uint32_t)(slot * 8 + t)) * 4u, wm,
                             peerMbar + (uint32_t)slot * 8u);
            }
        } else if ((j + 1) < JMAX) {
            // ===== group B: stage next emissions =====
            const float tm = sTm[k_l];
            sE[(j + 1) & 1][k_l][wp]     = (l0 + q0) * tm;
            sE[(j + 1) & 1][k_l][wp + 1] = (l1 + q1) * tm;
        }
        // no trailing sync: bar0 of next step provides ordering
    }

    // ---- final: wait last flight, logsumexp over full alpha row ----
    if (wid >= 8)
        wait_parity(myMbar + (uint32_t)((JMAX - 1) & 7) * 8u,
                    (uint32_t)(((JMAX - 1) >> 3) & 1));
    __syncthreads();
    {
        const int fslot = (JMAX - 1) & 7;
        float x = -1e30f;
        if (lane < 8)       x = sRedL[(JMAX - 1) & 3][lane];
        else if (lane < 16) x = sPmax[fslot][lane - 8];
        const float rowmax = funkey(redux_max_u32(fkey(x)));

        float sv = (tid < KK) ? __expf(sRing[fslot][tid] - rowmax) : 0.f;
        #pragma unroll
        for (int o = 16; o; o >>= 1) sv += __shfl_xor_sync(0xffffffffu, sv, o);
        if (lane == 0 && wid < 8) sRed[8 + wid] = sv;
        __syncthreads();
        if (r == 0 && tid == 0) {
            float ssum = 0.f;
            #pragma unroll
            for (int i = 0; i < 8; i++) ssum += sRed[8 + i];
            out[b] = rowmax + __logf(ssum);
        }
    }

    asm volatile("barrier.cluster.arrive.aligned;" ::: "memory");
    asm volatile("barrier.cluster.wait.aligned;"   ::: "memory");
}

// ---------------------------------------------------------------------------
extern "C" void kernel_launch(void* const* d_in, const int* in_sizes, int n_in,
                              void* d_out, int out_size) {
    const float* logits = (const float*)d_in[0];   // (B,S,W,K) f32
    const float* T      = (const float*)d_in[1];   // (B,K,K)   f32
    const float* hc     = (const float*)d_in[2];   // (B,S,W,K) f32
    const float* tagm   = (const float*)d_in[3];   // (B,K,K)   f32
    const int*   tmask  = (const int*)  d_in[4];   // (B,S)     i32
    float* out = (float*)d_out;                    // (1,B)     f32

    crf_hmma7_kernel<<<BB * 2, NT>>>(logits, T, hc, tagm, tmask, out);
}